// round 12
// baseline (speedup 1.0000x reference)
#include <cuda_runtime.h>
#include <cstdint>

typedef unsigned int u32;

#define BATCH   4
#define SEQ     2048
#define DIM     1024
#define HEADS   16
#define DH      64
#define MTOT    (BATCH*SEQ)
#define LOG2E      1.4426950408889634f
#define NEGBIG_L2  1.4426950408889634e10f
#define QSCL       (0.125f * LOG2E)

// ---------------------------------------------------------------------------
// helpers
// ---------------------------------------------------------------------------
__device__ __forceinline__ float to_tf32(float x) {
    float r; asm("cvt.rna.tf32.f32 %0, %1;" : "=f"(r) : "f"(x)); return r;
}
__device__ __forceinline__ float ex2(float x) {
    float r; asm("ex2.approx.ftz.f32 %0, %1;" : "=f"(r) : "f"(x)); return r;
}
__device__ __forceinline__ u32 su32(const void* p) {
    return (u32)__cvta_generic_to_shared(p);
}
__device__ __forceinline__ void ldsm4(u32 &r0, u32 &r1, u32 &r2, u32 &r3, u32 addr) {
    asm volatile("ldmatrix.sync.aligned.m8n8.x4.shared.b16 {%0,%1,%2,%3}, [%4];"
        : "=r"(r0), "=r"(r1), "=r"(r2), "=r"(r3) : "r"(addr));
}
__device__ __forceinline__ void mma_tf32(float &c0, float &c1, float &c2, float &c3,
                                         u32 a0, u32 a1, u32 a2, u32 a3,
                                         u32 b0, u32 b1) {
    asm volatile("mma.sync.aligned.m16n8k8.row.col.f32.tf32.tf32.f32 "
                 "{%0,%1,%2,%3}, {%4,%5,%6,%7}, {%8,%9}, {%0,%1,%2,%3};"
        : "+f"(c0), "+f"(c1), "+f"(c2), "+f"(c3)
        : "r"(a0), "r"(a1), "r"(a2), "r"(a3), "r"(b0), "r"(b1));
}
__device__ __forceinline__ void cpa16(u32 dst, const void* src) {
    asm volatile("cp.async.cg.shared.global [%0], [%1], 16;" :: "r"(dst), "l"(src));
}
__device__ __forceinline__ void cpa4(u32 dst, const void* src) {
    asm volatile("cp.async.ca.shared.global [%0], [%1], 4;" :: "r"(dst), "l"(src));
}
__device__ __forceinline__ void cp_commit() {
    asm volatile("cp.async.commit_group;" ::: "memory");
}
__device__ __forceinline__ void cp_wait0() {
    asm volatile("cp.async.wait_group 0;" ::: "memory");
}

// ---------------------------------------------------------------------------
// Scratch
// ---------------------------------------------------------------------------
__device__ float g_qw[(size_t)MTOT * DIM];     // Q proj, [b*S][h*dh], tf32
__device__ float g_kw[(size_t)MTOT * DIM];     // K proj, [b*S][h*dh], tf32
__device__ float g_vwt[(size_t)MTOT * DIM];    // V proj TRANSPOSED [b][h][d][s], tf32
__device__ float g_wqt[(size_t)DIM * DIM];     // W^T, tf32
__device__ float g_wkt[(size_t)DIM * DIM];
__device__ float g_wvt[(size_t)DIM * DIM];
__device__ float g_aq[(size_t)MTOT * DIM];     // rna-tf32-rounded inputs
__device__ float g_ak[(size_t)MTOT * DIM];
__device__ float g_av[(size_t)MTOT * DIM];

// ---------------------------------------------------------------------------
// elementwise rna->tf32 pre-pass
// ---------------------------------------------------------------------------
__global__ __launch_bounds__(256) void round_kernel(
    const float4* __restrict__ in, float4* __restrict__ out) {
    size_t i = (size_t)blockIdx.x * 256 + threadIdx.x;
    float4 v = in[i];
    v.x = to_tf32(v.x); v.y = to_tf32(v.y); v.z = to_tf32(v.z); v.w = to_tf32(v.w);
    out[i] = v;
}

// ---------------------------------------------------------------------------
// W transpose + tf32 round: Wt[n][k] = tf32(W[k][n])
// ---------------------------------------------------------------------------
__global__ void wtrans_kernel(const float* __restrict__ W, float* __restrict__ Wt) {
    __shared__ float t[32][33];
    int n0 = blockIdx.x * 32, k0 = blockIdx.y * 32;
    int tx = threadIdx.x, ty = threadIdx.y;
    #pragma unroll
    for (int i = 0; i < 4; i++)
        t[ty + 8 * i][tx] = to_tf32(W[(size_t)(k0 + ty + 8 * i) * DIM + n0 + tx]);
    __syncthreads();
    #pragma unroll
    for (int i = 0; i < 4; i++)
        Wt[(size_t)(n0 + ty + 8 * i) * DIM + k0 + tx] = t[tx][ty + 8 * i];
}

// ---------------------------------------------------------------------------
// Projection GEMM: C = A @ Wt^T. A, Wt both pre-rounded tf32.
// 128x128 tile, BK=32, 2-stage cp.async, 2 blocks/SM. 8 warps (4m x 2n).
// Pure LDSM+MMA inner loop (no in-register cvt).
// vmode=1: store transposed into [b][h][d][s].
// ---------------------------------------------------------------------------
#define PSTR 36
#define PSTG (128 * PSTR)

__global__ __launch_bounds__(256, 2) void proj_kernel(
    const float* __restrict__ A,
    const float* __restrict__ Wt,
    float* __restrict__ C,
    int vmode)
{
    extern __shared__ float ps[];
    float* As = ps;                 // 2 stages x 128 x PSTR
    float* Ws = ps + 2 * PSTG;

    const int tid  = threadIdx.x;
    const int lane = tid & 31;
    const int warp = tid >> 5;
    const int wm = warp >> 1;
    const int wn = warp & 1;
    const int row0 = blockIdx.y * 128;
    const int col0 = blockIdx.x * 128;
    const int rsel = (lane & 7) + ((lane >> 3) & 1) * 8;

    float acc[2][8][4];
    #pragma unroll
    for (int i = 0; i < 2; i++)
        #pragma unroll
        for (int j = 0; j < 8; j++)
            #pragma unroll
            for (int r = 0; r < 4; r++) acc[i][j][r] = 0.f;

    // stage-0 issue
    {
        #pragma unroll
        for (int p = 0; p < 4; p++) {
            int idx = tid + p * 256;
            int r = idx >> 3, c4 = idx & 7;
            cpa16(su32(As + r * PSTR + 4 * c4), &A[(size_t)(row0 + r) * DIM + 4 * c4]);
            cpa16(su32(Ws + r * PSTR + 4 * c4), &Wt[(size_t)(col0 + r) * DIM + 4 * c4]);
        }
        cp_commit();
    }

    for (int t = 0; t < DIM / 32; t++) {
        int buf = t & 1;
        cp_wait0();
        __syncthreads();
        if (t < DIM / 32 - 1) {
            int kt = (t + 1) * 32;
            float* Ad = As + (buf ^ 1) * PSTG;
            float* Wd = Ws + (buf ^ 1) * PSTG;
            #pragma unroll
            for (int p = 0; p < 4; p++) {
                int idx = tid + p * 256;
                int r = idx >> 3, c4 = idx & 7;
                cpa16(su32(Ad + r * PSTR + 4 * c4), &A[(size_t)(row0 + r) * DIM + kt + 4 * c4]);
                cpa16(su32(Wd + r * PSTR + 4 * c4), &Wt[(size_t)(col0 + r) * DIM + kt + 4 * c4]);
            }
            cp_commit();
        }
        float* Ab = As + buf * PSTG;
        float* Wb = Ws + buf * PSTG;

        #pragma unroll
        for (int ks = 0; ks < 4; ks++) {
            int chunk = 2 * ks + (lane >> 4);
            u32 a[2][4];
            #pragma unroll
            for (int mf = 0; mf < 2; mf++) {
                int row = wm * 32 + mf * 16 + rsel;
                ldsm4(a[mf][0], a[mf][1], a[mf][2], a[mf][3],
                      su32(Ab + row * PSTR + 4 * chunk));
            }
            u32 b[8][2];
            #pragma unroll
            for (int nfp = 0; nfp < 4; nfp++) {
                int row = wn * 64 + nfp * 16 + rsel;
                u32 r0, r1, r2, r3;
                ldsm4(r0, r1, r2, r3, su32(Wb + row * PSTR + 4 * chunk));
                b[2 * nfp][0] = r0; b[2 * nfp][1] = r2;
                b[2 * nfp + 1][0] = r1; b[2 * nfp + 1][1] = r3;
            }
            #pragma unroll
            for (int mf = 0; mf < 2; mf++)
                #pragma unroll
                for (int nf = 0; nf < 8; nf++)
                    mma_tf32(acc[mf][nf][0], acc[mf][nf][1], acc[mf][nf][2], acc[mf][nf][3],
                             a[mf][0], a[mf][1], a[mf][2], a[mf][3],
                             b[nf][0], b[nf][1]);
        }
        __syncthreads();
    }

    const int g = lane >> 2;
    const int tg = lane & 3;
    if (!vmode) {
        #pragma unroll
        for (int mf = 0; mf < 2; mf++) {
            int r = row0 + wm * 32 + mf * 16 + g;
            #pragma unroll
            for (int nf = 0; nf < 8; nf++) {
                int c = col0 + wn * 64 + 8 * nf + 2 * tg;
                *(float2*)&C[(size_t)r * DIM + c] =
                    make_float2(to_tf32(acc[mf][nf][0]), to_tf32(acc[mf][nf][1]));
                *(float2*)&C[(size_t)(r + 8) * DIM + c] =
                    make_float2(to_tf32(acc[mf][nf][2]), to_tf32(acc[mf][nf][3]));
            }
        }
    } else {
        // transposed store: C[((b*H + h)*DH + d)*SEQ + s]
        #pragma unroll
        for (int mf = 0; mf < 2; mf++) {
            int r = row0 + wm * 32 + mf * 16 + g;
            int bb = r >> 11, s1 = r & (SEQ - 1);
            #pragma unroll
            for (int nf = 0; nf < 8; nf++) {
                int c = col0 + wn * 64 + 8 * nf + 2 * tg;
                int h = c >> 6, d = c & 63;
                size_t base = ((size_t)(bb * HEADS + h) * DH + d) * SEQ + s1;
                C[base]           = to_tf32(acc[mf][nf][0]);
                C[base + SEQ]     = to_tf32(acc[mf][nf][1]);
                C[base + 8]       = to_tf32(acc[mf][nf][2]);
                C[base + SEQ + 8] = to_tf32(acc[mf][nf][3]);
            }
        }
    }
}

// ---------------------------------------------------------------------------
// Flash attention (round-9, known-good): 128 thr / 4 warps. BQ=128,
// BKV=64, 2-stage cp.async K + V^T. Q frags register-resident; P reuses QP.
// ---------------------------------------------------------------------------
#define ASTR 68
#define AK_OFF (128 * ASTR)
#define AV_OFF (AK_OFF + 2 * 64 * ASTR)
#define AM_OFF (AV_OFF + 2 * 64 * ASTR)
#define A_SMEM_FLOATS (AM_OFF + 2 * 64)

__global__ __launch_bounds__(128) void attn_kernel(
    const float* __restrict__ qw,
    const float* __restrict__ kw,
    const float* __restrict__ vwt,
    const float* __restrict__ v_mask,
    const float* __restrict__ q_mask,
    float* __restrict__ out)
{
    extern __shared__ float smem[];
    float* QP  = smem;
    float* Ksm = smem + AK_OFF;
    float* Vsm = smem + AV_OFF;
    float* Msm = smem + AM_OFF;

    const int tid  = threadIdx.x;
    const int lane = tid & 31;
    const int warp = tid >> 5;
    const int g  = lane >> 2;
    const int tg = lane & 3;
    const int q0 = blockIdx.x * 128;
    const int bh = blockIdx.y;
    const int b = bh / HEADS;
    const int h = bh % HEADS;
    const int rsel = (lane & 7) + ((lane >> 3) & 1) * 8;

    const float* qbase  = qw  + (size_t)(b * SEQ + q0) * DIM + h * DH;
    const float* kbase0 = kw  + (size_t)(b * SEQ) * DIM + h * DH;
    const float* vtbase = vwt + (size_t)(b * HEADS + h) * DH * SEQ;

    #pragma unroll
    for (int p = 0; p < 16; p++) {
        int idx = tid + p * 128;
        int r  = idx >> 4;
        int c4 = idx & 15;
        float4 v = *(const float4*)&qbase[(size_t)r * DIM + 4 * c4];
        v.x = to_tf32(v.x * QSCL); v.y = to_tf32(v.y * QSCL);
        v.z = to_tf32(v.z * QSCL); v.w = to_tf32(v.w * QSCL);
        *(float4*)&QP[r * ASTR + 4 * c4] = v;
    }
    __syncthreads();

    u32 qa[2][8][4];
    #pragma unroll
    for (int mf = 0; mf < 2; mf++)
        #pragma unroll
        for (int ks = 0; ks < 8; ks++) {
            int row = warp * 32 + mf * 16 + rsel;
            int chunk = 2 * ks + (lane >> 4);
            ldsm4(qa[mf][ks][0], qa[mf][ks][1], qa[mf][ks][2], qa[mf][ks][3],
                  su32(&QP[row * ASTR + 4 * chunk]));
        }
    __syncthreads();

    float m_i[4] = {-1e30f, -1e30f, -1e30f, -1e30f};
    float l_i[4] = {0.f, 0.f, 0.f, 0.f};
    float o[2][8][4];
    #pragma unroll
    for (int mf = 0; mf < 2; mf++)
        #pragma unroll
        for (int nf = 0; nf < 8; nf++)
            #pragma unroll
            for (int r = 0; r < 4; r++) o[mf][nf][r] = 0.f;

    {
        #pragma unroll
        for (int p = 0; p < 8; p++) {
            int idx = tid + p * 128;
            int r = idx >> 4, c4 = idx & 15;
            cpa16(su32(Ksm + r * ASTR + 4 * c4), kbase0 + (size_t)r * DIM + 4 * c4);
            cpa16(su32(Vsm + r * ASTR + 4 * c4), vtbase + (size_t)r * SEQ + 4 * c4);
        }
        if (tid < 64) cpa4(su32(Msm + tid), v_mask + b * SEQ + tid);
        cp_commit();
    }

    for (int kt = 0; kt < SEQ / 64; kt++) {
        int buf = kt & 1;
        cp_wait0();
        __syncthreads();
        if (kt < SEQ / 64 - 1) {
            int c1 = (kt + 1) * 64;
            float* Kd = Ksm + (buf ^ 1) * 64 * ASTR;
            float* Vd = Vsm + (buf ^ 1) * 64 * ASTR;
            const float* kb = kbase0 + (size_t)c1 * DIM;
            #pragma unroll
            for (int p = 0; p < 8; p++) {
                int idx = tid + p * 128;
                int r = idx >> 4, c4 = idx & 15;
                cpa16(su32(Kd + r * ASTR + 4 * c4), kb + (size_t)r * DIM + 4 * c4);
                cpa16(su32(Vd + r * ASTR + 4 * c4), vtbase + (size_t)r * SEQ + c1 + 4 * c4);
            }
            if (tid < 64) cpa4(su32(Msm + (buf ^ 1) * 64 + tid), v_mask + b * SEQ + c1 + tid);
            cp_commit();
        }
        float* Kb = Ksm + buf * 64 * ASTR;
        float* Vb = Vsm + buf * 64 * ASTR;
        float* Mb = Msm + buf * 64;

        float s[2][8][4];
        #pragma unroll
        for (int mf = 0; mf < 2; mf++)
            #pragma unroll
            for (int nf = 0; nf < 8; nf++)
                #pragma unroll
                for (int r = 0; r < 4; r++) s[mf][nf][r] = 0.f;

        #pragma unroll
        for (int ks = 0; ks < 8; ks++) {
            int chunk = 2 * ks + (lane >> 4);
            u32 kb2[8][2];
            #pragma unroll
            for (int nfp = 0; nfp < 4; nfp++) {
                int row = nfp * 16 + rsel;
                u32 r0, r1, r2, r3;
                ldsm4(r0, r1, r2, r3, su32(Kb + row * ASTR + 4 * chunk));
                kb2[2 * nfp][0] = r0; kb2[2 * nfp][1] = r2;
                kb2[2 * nfp + 1][0] = r1; kb2[2 * nfp + 1][1] = r3;
            }
            #pragma unroll
            for (int mf = 0; mf < 2; mf++)
                #pragma unroll
                for (int nf = 0; nf < 8; nf++)
                    mma_tf32(s[mf][nf][0], s[mf][nf][1], s[mf][nf][2], s[mf][nf][3],
                             qa[mf][ks][0], qa[mf][ks][1], qa[mf][ks][2], qa[mf][ks][3],
                             kb2[nf][0], kb2[nf][1]);
        }

        #pragma unroll
        for (int nf = 0; nf < 8; nf++) {
            int col = 8 * nf + 2 * tg;
            float m0 = (1.0f - Mb[col])     * NEGBIG_L2;
            float m1 = (1.0f - Mb[col + 1]) * NEGBIG_L2;
            #pragma unroll
            for (int mf = 0; mf < 2; mf++) {
                s[mf][nf][0] -= m0; s[mf][nf][1] -= m1;
                s[mf][nf][2] -= m0; s[mf][nf][3] -= m1;
            }
        }

        #pragma unroll
        for (int mf = 0; mf < 2; mf++) {
            float rmax0 = -1e30f, rmax1 = -1e30f;
            #pragma unroll
            for (int nf = 0; nf < 8; nf++) {
                rmax0 = fmaxf(rmax0, fmaxf(s[mf][nf][0], s[mf][nf][1]));
                rmax1 = fmaxf(rmax1, fmaxf(s[mf][nf][2], s[mf][nf][3]));
            }
            #pragma unroll
            for (int off = 1; off <= 2; off <<= 1) {
                rmax0 = fmaxf(rmax0, __shfl_xor_sync(0xffffffffu, rmax0, off));
                rmax1 = fmaxf(rmax1, __shfl_xor_sync(0xffffffffu, rmax1, off));
            }
            float mn0 = fmaxf(m_i[2 * mf],     rmax0);
            float mn1 = fmaxf(m_i[2 * mf + 1], rmax1);
            float fi0 = ex2(m_i[2 * mf]     - mn0);
            float fi1 = ex2(m_i[2 * mf + 1] - mn1);
            m_i[2 * mf] = mn0; m_i[2 * mf + 1] = mn1;
            l_i[2 * mf] *= fi0; l_i[2 * mf + 1] *= fi1;
            #pragma unroll
            for (int nf = 0; nf < 8; nf++) {
                o[mf][nf][0] *= fi0; o[mf][nf][1] *= fi0;
                o[mf][nf][2] *= fi1; o[mf][nf][3] *= fi1;
            }
            float ls0 = 0.f, ls1 = 0.f;
            #pragma unroll
            for (int nf = 0; nf < 8; nf++) {
                s[mf][nf][0] = ex2(s[mf][nf][0] - mn0);
                s[mf][nf][1] = ex2(s[mf][nf][1] - mn0);
                s[mf][nf][2] = ex2(s[mf][nf][2] - mn1);
                s[mf][nf][3] = ex2(s[mf][nf][3] - mn1);
                ls0 += s[mf][nf][0] + s[mf][nf][1];
                ls1 += s[mf][nf][2] + s[mf][nf][3];
            }
            #pragma unroll
            for (int off = 1; off <= 2; off <<= 1) {
                ls0 += __shfl_xor_sync(0xffffffffu, ls0, off);
                ls1 += __shfl_xor_sync(0xffffffffu, ls1, off);
            }
            l_i[2 * mf] += ls0; l_i[2 * mf + 1] += ls1;
        }

        #pragma unroll
        for (int mf = 0; mf < 2; mf++) {
            int row = warp * 32 + mf * 16 + g;
            #pragma unroll
            for (int nf = 0; nf < 8; nf++) {
                int col = 8 * nf + 2 * tg;
                *(float2*)&QP[row * ASTR + col] =
                    make_float2(to_tf32(s[mf][nf][0]), to_tf32(s[mf][nf][1]));
                *(float2*)&QP[(row + 8) * ASTR + col] =
                    make_float2(to_tf32(s[mf][nf][2]), to_tf32(s[mf][nf][3]));
            }
        }
        __syncwarp();

        #pragma unroll
        for (int ks = 0; ks < 8; ks++) {
            int chunk = 2 * ks + (lane >> 4);
            u32 pa[2][4];
            #pragma unroll
            for (int mf = 0; mf < 2; mf++) {
                int row = warp * 32 + mf * 16 + rsel;
                ldsm4(pa[mf][0], pa[mf][1], pa[mf][2], pa[mf][3],
                      su32(&QP[row * ASTR + 4 * chunk]));
            }
            u32 vb2[8][2];
            #pragma unroll
            for (int nfp = 0; nfp < 4; nfp++) {
                int row = nfp * 16 + rsel;
                u32 r0, r1, r2, r3;
                ldsm4(r0, r1, r2, r3, su32(Vb + row * ASTR + 4 * chunk));
                vb2[2 * nfp][0] = r0; vb2[2 * nfp][1] = r2;
                vb2[2 * nfp + 1][0] = r1; vb2[2 * nfp + 1][1] = r3;
            }
            #pragma unroll
            for (int mf = 0; mf < 2; mf++)
                #pragma unroll
                for (int nf = 0; nf < 8; nf++)
                    mma_tf32(o[mf][nf][0], o[mf][nf][1], o[mf][nf][2], o[mf][nf][3],
                             pa[mf][0], pa[mf][1], pa[mf][2], pa[mf][3],
                             vb2[nf][0], vb2[nf][1]);
        }
        __syncthreads();
    }

    #pragma unroll
    for (int mf = 0; mf < 2; mf++) {
        int r0g = q0 + warp * 32 + mf * 16 + g;
        int r1g = r0g + 8;
        float inv0 = (l_i[2 * mf]     > 0.f) ? 1.0f / l_i[2 * mf]     : 0.f;
        float inv1 = (l_i[2 * mf + 1] > 0.f) ? 1.0f / l_i[2 * mf + 1] : 0.f;
        float qm0 = q_mask[b * SEQ + r0g] * inv0;
        float qm1 = q_mask[b * SEQ + r1g] * inv1;
        #pragma unroll
        for (int nf = 0; nf < 8; nf++) {
            int c = h * DH + 8 * nf + 2 * tg;
            *(float2*)&out[(size_t)(b * SEQ + r0g) * DIM + c] =
                make_float2(o[mf][nf][0] * qm0, o[mf][nf][1] * qm0);
            *(float2*)&out[(size_t)(b * SEQ + r1g) * DIM + c] =
                make_float2(o[mf][nf][2] * qm1, o[mf][nf][3] * qm1);
        }
    }
}

// ---------------------------------------------------------------------------
// Launch
// ---------------------------------------------------------------------------
extern "C" void kernel_launch(void* const* d_in, const int* in_sizes, int n_in,
                              void* d_out, int out_size)
{
    const float* q_value = (const float*)d_in[0];
    const float* k_value = (const float*)d_in[1];
    const float* v_value = (const float*)d_in[2];
    const float* v_mask  = (const float*)d_in[3];
    const float* q_mask  = (const float*)d_in[4];
    const float* Wq      = (const float*)d_in[5];
    const float* Wk      = (const float*)d_in[6];
    const float* Wv      = (const float*)d_in[7];
    float* out = (float*)d_out;

    float *qw, *kw, *vwt, *wqt, *wkt, *wvt, *aq, *ak, *av;
    cudaGetSymbolAddress((void**)&qw,  g_qw);
    cudaGetSymbolAddress((void**)&kw,  g_kw);
    cudaGetSymbolAddress((void**)&vwt, g_vwt);
    cudaGetSymbolAddress((void**)&wqt, g_wqt);
    cudaGetSymbolAddress((void**)&wkt, g_wkt);
    cudaGetSymbolAddress((void**)&wvt, g_wvt);
    cudaGetSymbolAddress((void**)&aq,  g_aq);
    cudaGetSymbolAddress((void**)&ak,  g_ak);
    cudaGetSymbolAddress((void**)&av,  g_av);

    int rGrid = (MTOT * DIM / 4) / 256;     // 8192
    round_kernel<<<rGrid, 256>>>((const float4*)q_value, (float4*)aq);
    round_kernel<<<rGrid, 256>>>((const float4*)k_value, (float4*)ak);
    round_kernel<<<rGrid, 256>>>((const float4*)v_value, (float4*)av);

    dim3 wtG(DIM / 32, DIM / 32), wtB(32, 8);
    wtrans_kernel<<<wtG, wtB>>>(Wq, wqt);
    wtrans_kernel<<<wtG, wtB>>>(Wk, wkt);
    wtrans_kernel<<<wtG, wtB>>>(Wv, wvt);

    const int proj_smem = 4 * PSTG * (int)sizeof(float);   // 73728
    cudaFuncSetAttribute(proj_kernel,
                         cudaFuncAttributeMaxDynamicSharedMemorySize, proj_smem);
    dim3 pGrid(DIM / 128, MTOT / 128);   // (8, 64)
    proj_kernel<<<pGrid, 256, proj_smem>>>(aq, wqt, qw, 0);
    proj_kernel<<<pGrid, 256, proj_smem>>>(ak, wkt, kw, 0);
    proj_kernel<<<pGrid, 256, proj_smem>>>(av, wvt, vwt, 1);

    const int attn_smem = A_SMEM_FLOATS * (int)sizeof(float);
    cudaFuncSetAttribute(attn_kernel,
                         cudaFuncAttributeMaxDynamicSharedMemorySize, attn_smem);
    dim3 aGrid(SEQ / 128, BATCH * HEADS);   // (16, 64)
    attn_kernel<<<aGrid, 128, attn_smem>>>(qw, kw, vwt, v_mask, q_mask, out);
}

// round 13
// speedup vs baseline: 1.6884x; 1.6884x over previous
#include <cuda_runtime.h>
#include <cuda_fp16.h>
#include <cstdint>

typedef unsigned int u32;

#define BATCH   4
#define SEQ     2048
#define DIM     1024
#define HEADS   16
#define DH      64
#define MTOT    (BATCH*SEQ)
#define LOG2E      1.4426950408889634f
#define NEGBIG_L2  1.4426950408889634e10f
#define QSCL       (0.125f * LOG2E)

// ---------------------------------------------------------------------------
// helpers
// ---------------------------------------------------------------------------
__device__ __forceinline__ float ex2(float x) {
    float r; asm("ex2.approx.ftz.f32 %0, %1;" : "=f"(r) : "f"(x)); return r;
}
__device__ __forceinline__ u32 su32(const void* p) {
    return (u32)__cvta_generic_to_shared(p);
}
__device__ __forceinline__ void ldsm4(u32 &r0, u32 &r1, u32 &r2, u32 &r3, u32 addr) {
    asm volatile("ldmatrix.sync.aligned.m8n8.x4.shared.b16 {%0,%1,%2,%3}, [%4];"
        : "=r"(r0), "=r"(r1), "=r"(r2), "=r"(r3) : "r"(addr));
}
__device__ __forceinline__ void mma_f16(float &c0, float &c1, float &c2, float &c3,
                                        u32 a0, u32 a1, u32 a2, u32 a3,
                                        u32 b0, u32 b1) {
    asm volatile("mma.sync.aligned.m16n8k16.row.col.f32.f16.f16.f32 "
                 "{%0,%1,%2,%3}, {%4,%5,%6,%7}, {%8,%9}, {%0,%1,%2,%3};"
        : "+f"(c0), "+f"(c1), "+f"(c2), "+f"(c3)
        : "r"(a0), "r"(a1), "r"(a2), "r"(a3), "r"(b0), "r"(b1));
}
__device__ __forceinline__ void cpa16(u32 dst, const void* src) {
    asm volatile("cp.async.cg.shared.global [%0], [%1], 16;" :: "r"(dst), "l"(src));
}
__device__ __forceinline__ void cpa4(u32 dst, const void* src) {
    asm volatile("cp.async.ca.shared.global [%0], [%1], 4;" :: "r"(dst), "l"(src));
}
__device__ __forceinline__ void cp_commit() {
    asm volatile("cp.async.commit_group;" ::: "memory");
}
__device__ __forceinline__ void cp_wait0() {
    asm volatile("cp.async.wait_group 0;" ::: "memory");
}
__device__ __forceinline__ u32 h2u(__half2 h) {
    u32 r; __builtin_memcpy(&r, &h, 4); return r;
}

// ---------------------------------------------------------------------------
// Scratch (all fp16)
// ---------------------------------------------------------------------------
__device__ __half g_qw[(size_t)MTOT * DIM];    // Q proj (pre-scaled by QSCL)
__device__ __half g_kw[(size_t)MTOT * DIM];    // K proj
__device__ __half g_vwt[(size_t)MTOT * DIM];   // V proj transposed [b][h][d][s]
__device__ __half g_wqt[(size_t)DIM * DIM];    // W^T
__device__ __half g_wkt[(size_t)DIM * DIM];
__device__ __half g_wvt[(size_t)DIM * DIM];
__device__ __half g_ah[(size_t)MTOT * DIM];    // fp16-rounded inputs
__device__ __half g_kh[(size_t)MTOT * DIM];
__device__ __half g_vh[(size_t)MTOT * DIM];

// ---------------------------------------------------------------------------
// elementwise fp32 -> fp16 pre-pass (8 elements / thread)
// ---------------------------------------------------------------------------
__global__ __launch_bounds__(256) void round_kernel(
    const float4* __restrict__ in, uint4* __restrict__ out)
{
    size_t i = (size_t)blockIdx.x * 256 + threadIdx.x;
    float4 v0 = in[2 * i], v1 = in[2 * i + 1];
    uint4 o;
    o.x = h2u(__floats2half2_rn(v0.x, v0.y));
    o.y = h2u(__floats2half2_rn(v0.z, v0.w));
    o.z = h2u(__floats2half2_rn(v1.x, v1.y));
    o.w = h2u(__floats2half2_rn(v1.z, v1.w));
    out[i] = o;
}

// ---------------------------------------------------------------------------
// W transpose + fp16 round: Wt[n][k] = h(W[k][n])
// ---------------------------------------------------------------------------
__global__ void wtrans_kernel(const float* __restrict__ W, __half* __restrict__ Wt) {
    __shared__ float t[32][33];
    int n0 = blockIdx.x * 32, k0 = blockIdx.y * 32;
    int tx = threadIdx.x, ty = threadIdx.y;
    #pragma unroll
    for (int i = 0; i < 4; i++)
        t[ty + 8 * i][tx] = W[(size_t)(k0 + ty + 8 * i) * DIM + n0 + tx];
    __syncthreads();
    #pragma unroll
    for (int i = 0; i < 4; i++)
        Wt[(size_t)(n0 + ty + 8 * i) * DIM + k0 + tx] = __float2half_rn(t[tx][ty + 8 * i]);
}

// ---------------------------------------------------------------------------
// fp16 projection GEMM: C = A @ Wt^T (fp32 accum), 128x128 tile, BK=32,
// 2-stage cp.async, 8 warps (4m x 2n), warp tile 32x64, m16n8k16.
// oscale folded into output; vmode=1 stores transposed [b][h][d][s].
// ---------------------------------------------------------------------------
#define PSTR 40              // halfs per row (80B, conflict-free ldsm)
#define PSTG (128 * PSTR)    // halfs per stage

__global__ __launch_bounds__(256, 2) void proj_kernel(
    const __half* __restrict__ A,
    const __half* __restrict__ Wt,
    __half* __restrict__ C,
    int vmode, float oscale)
{
    extern __shared__ __half ps[];
    __half* As = ps;                 // 2 stages x 128 x PSTR
    __half* Ws = ps + 2 * PSTG;

    const int tid  = threadIdx.x;
    const int lane = tid & 31;
    const int warp = tid >> 5;
    const int wm = warp >> 1;
    const int wn = warp & 1;
    const int row0 = blockIdx.y * 128;
    const int col0 = blockIdx.x * 128;
    const int r16  = lane & 15;
    const int hi16 = (lane >> 4) * 16;   // byte offset for upper 16 lanes

    float acc[2][8][4];
    #pragma unroll
    for (int i = 0; i < 2; i++)
        #pragma unroll
        for (int j = 0; j < 8; j++)
            #pragma unroll
            for (int r = 0; r < 4; r++) acc[i][j][r] = 0.f;

    // stage-0 issue
    {
        #pragma unroll
        for (int p = 0; p < 2; p++) {
            int idx = tid + p * 256;
            int r = idx >> 2, cb = idx & 3;
            cpa16(su32(As + r * PSTR + cb * 8), A  + (size_t)(row0 + r) * DIM + cb * 8);
            cpa16(su32(Ws + r * PSTR + cb * 8), Wt + (size_t)(col0 + r) * DIM + cb * 8);
        }
        cp_commit();
    }

    for (int t = 0; t < DIM / 32; t++) {
        int buf = t & 1;
        cp_wait0();
        __syncthreads();
        if (t < DIM / 32 - 1) {
            int kt = (t + 1) * 32;
            __half* Ad = As + (buf ^ 1) * PSTG;
            __half* Wd = Ws + (buf ^ 1) * PSTG;
            #pragma unroll
            for (int p = 0; p < 2; p++) {
                int idx = tid + p * 256;
                int r = idx >> 2, cb = idx & 3;
                cpa16(su32(Ad + r * PSTR + cb * 8), A  + (size_t)(row0 + r) * DIM + kt + cb * 8);
                cpa16(su32(Wd + r * PSTR + cb * 8), Wt + (size_t)(col0 + r) * DIM + kt + cb * 8);
            }
            cp_commit();
        }
        __half* Ab = As + buf * PSTG;
        __half* Wb = Ws + buf * PSTG;

        #pragma unroll
        for (int ks = 0; ks < 2; ks++) {
            u32 a[2][4];
            #pragma unroll
            for (int mf = 0; mf < 2; mf++) {
                int row = wm * 32 + mf * 16 + r16;
                ldsm4(a[mf][0], a[mf][1], a[mf][2], a[mf][3],
                      su32(Ab + row * PSTR) + ks * 32 + hi16);
            }
            u32 b[8][2];
            #pragma unroll
            for (int nfp = 0; nfp < 4; nfp++) {
                int row = wn * 64 + nfp * 16 + r16;
                u32 r0, r1, r2, r3;
                ldsm4(r0, r1, r2, r3, su32(Wb + row * PSTR) + ks * 32 + hi16);
                b[2 * nfp][0] = r0;     b[2 * nfp][1] = r2;
                b[2 * nfp + 1][0] = r1; b[2 * nfp + 1][1] = r3;
            }
            #pragma unroll
            for (int mf = 0; mf < 2; mf++)
                #pragma unroll
                for (int nf = 0; nf < 8; nf++)
                    mma_f16(acc[mf][nf][0], acc[mf][nf][1], acc[mf][nf][2], acc[mf][nf][3],
                            a[mf][0], a[mf][1], a[mf][2], a[mf][3],
                            b[nf][0], b[nf][1]);
        }
        __syncthreads();
    }

    const int g = lane >> 2;
    const int tg = lane & 3;
    if (!vmode) {
        #pragma unroll
        for (int mf = 0; mf < 2; mf++) {
            int r = row0 + wm * 32 + mf * 16 + g;
            #pragma unroll
            for (int nf = 0; nf < 8; nf++) {
                int c = col0 + wn * 64 + 8 * nf + 2 * tg;
                *(__half2*)&C[(size_t)r * DIM + c] =
                    __floats2half2_rn(acc[mf][nf][0] * oscale, acc[mf][nf][1] * oscale);
                *(__half2*)&C[(size_t)(r + 8) * DIM + c] =
                    __floats2half2_rn(acc[mf][nf][2] * oscale, acc[mf][nf][3] * oscale);
            }
        }
    } else {
        // transposed store: C[((b*H + h)*DH + d)*SEQ + s]
        #pragma unroll
        for (int mf = 0; mf < 2; mf++) {
            int r = row0 + wm * 32 + mf * 16 + g;
            int bb = r >> 11, s1 = r & (SEQ - 1);
            #pragma unroll
            for (int nf = 0; nf < 8; nf++) {
                int c = col0 + wn * 64 + 8 * nf + 2 * tg;
                int h = c >> 6, d = c & 63;
                size_t base = ((size_t)(bb * HEADS + h) * DH + d) * SEQ + s1;
                C[base]           = __float2half_rn(acc[mf][nf][0]);
                C[base + SEQ]     = __float2half_rn(acc[mf][nf][1]);
                C[base + 8]       = __float2half_rn(acc[mf][nf][2]);
                C[base + SEQ + 8] = __float2half_rn(acc[mf][nf][3]);
            }
        }
    }
}

// ---------------------------------------------------------------------------
// fp16 flash attention: 128 thr / 4 warps. BQ=128 (2 m-frags/warp), BKV=64,
// 2-stage cp.async K + V^T, m16n8k16, fp32 S/O. P reuses the Q smem tile.
// smem (halfs unless noted): QP[128*72] | K[2][64*72] | V[2][64*72] | maskF[2][64]
// ---------------------------------------------------------------------------
#define ASTR 72
#define AQP_B 0
#define AK_B  (128 * ASTR * 2)               // 18432
#define AV_B  (AK_B + 2 * 64 * ASTR * 2)     // 36864
#define AM_B  (AV_B + 2 * 64 * ASTR * 2)     // 55296
#define A_SMEM_BYTES (AM_B + 2 * 64 * 4)     // 55808

__global__ __launch_bounds__(128) void attn_kernel(
    const __half* __restrict__ qw,
    const __half* __restrict__ kw,
    const __half* __restrict__ vwt,
    const float* __restrict__ v_mask,
    const float* __restrict__ q_mask,
    float* __restrict__ out)
{
    extern __shared__ char asm_[];
    __half* QP  = (__half*)(asm_ + AQP_B);
    __half* Ksm = (__half*)(asm_ + AK_B);
    __half* Vsm = (__half*)(asm_ + AV_B);
    float*  Msm = (float*)(asm_ + AM_B);

    const int tid  = threadIdx.x;
    const int lane = tid & 31;
    const int warp = tid >> 5;
    const int g  = lane >> 2;
    const int tg = lane & 3;
    const int q0 = blockIdx.x * 128;
    const int bh = blockIdx.y;
    const int b = bh / HEADS;
    const int h = bh % HEADS;
    const int r16  = lane & 15;
    const int hi16 = (lane >> 4) * 16;

    const __half* qbase  = qw  + (size_t)(b * SEQ + q0) * DIM + h * DH;
    const __half* kbase0 = kw  + (size_t)(b * SEQ) * DIM + h * DH;
    const __half* vtbase = vwt + (size_t)(b * HEADS + h) * DH * SEQ;

    // ---- Q tile -> smem (already QSCL-scaled at projection) ----
    #pragma unroll
    for (int p = 0; p < 8; p++) {
        int idx = tid + p * 128;
        int r = idx >> 3, cb = idx & 7;
        cpa16(su32(QP + r * ASTR + cb * 8), qbase + (size_t)r * DIM + cb * 8);
    }
    cp_commit(); cp_wait0();
    __syncthreads();

    // ---- Q fragments: 2 m-frags x 4 k16-steps, register resident ----
    u32 qa[2][4][4];
    #pragma unroll
    for (int mf = 0; mf < 2; mf++)
        #pragma unroll
        for (int ks = 0; ks < 4; ks++) {
            int row = warp * 32 + mf * 16 + r16;
            ldsm4(qa[mf][ks][0], qa[mf][ks][1], qa[mf][ks][2], qa[mf][ks][3],
                  su32(QP + row * ASTR) + ks * 32 + hi16);
        }
    __syncthreads();   // QP free for P reuse

    float m_i[4] = {-1e30f, -1e30f, -1e30f, -1e30f};
    float l_i[4] = {0.f, 0.f, 0.f, 0.f};
    float o[2][8][4];
    #pragma unroll
    for (int mf = 0; mf < 2; mf++)
        #pragma unroll
        for (int nf = 0; nf < 8; nf++)
            #pragma unroll
            for (int r = 0; r < 4; r++) o[mf][nf][r] = 0.f;

    // stage-0 issue
    {
        #pragma unroll
        for (int p = 0; p < 4; p++) {
            int idx = tid + p * 128;
            int r = idx >> 3, cb = idx & 7;
            cpa16(su32(Ksm + r * ASTR + cb * 8), kbase0 + (size_t)r * DIM + cb * 8);
            cpa16(su32(Vsm + r * ASTR + cb * 8), vtbase + (size_t)r * SEQ + cb * 8);
        }
        if (tid < 64) cpa4(su32(Msm + tid), v_mask + b * SEQ + tid);
        cp_commit();
    }

    for (int kt = 0; kt < SEQ / 64; kt++) {
        int buf = kt & 1;
        cp_wait0();
        __syncthreads();
        if (kt < SEQ / 64 - 1) {
            int c1 = (kt + 1) * 64;
            __half* Kd = Ksm + (buf ^ 1) * 64 * ASTR;
            __half* Vd = Vsm + (buf ^ 1) * 64 * ASTR;
            const __half* kb = kbase0 + (size_t)c1 * DIM;
            #pragma unroll
            for (int p = 0; p < 4; p++) {
                int idx = tid + p * 128;
                int r = idx >> 3, cb = idx & 7;
                cpa16(su32(Kd + r * ASTR + cb * 8), kb + (size_t)r * DIM + cb * 8);
                cpa16(su32(Vd + r * ASTR + cb * 8), vtbase + (size_t)r * SEQ + c1 + cb * 8);
            }
            if (tid < 64) cpa4(su32(Msm + (buf ^ 1) * 64 + tid), v_mask + b * SEQ + c1 + tid);
            cp_commit();
        }
        __half* Kb = Ksm + buf * 64 * ASTR;
        __half* Vb = Vsm + buf * 64 * ASTR;
        float*  Mb = Msm + buf * 64;

        // ---- S = Q K^T (log2 domain) ----
        float s[2][8][4];
        #pragma unroll
        for (int mf = 0; mf < 2; mf++)
            #pragma unroll
            for (int nf = 0; nf < 8; nf++)
                #pragma unroll
                for (int r = 0; r < 4; r++) s[mf][nf][r] = 0.f;

        #pragma unroll
        for (int ks = 0; ks < 4; ks++) {
            u32 kb2[8][2];
            #pragma unroll
            for (int nfp = 0; nfp < 4; nfp++) {
                int row = nfp * 16 + r16;
                u32 r0, r1, r2, r3;
                ldsm4(r0, r1, r2, r3, su32(Kb + row * ASTR) + ks * 32 + hi16);
                kb2[2 * nfp][0] = r0;     kb2[2 * nfp][1] = r2;
                kb2[2 * nfp + 1][0] = r1; kb2[2 * nfp + 1][1] = r3;
            }
            #pragma unroll
            for (int mf = 0; mf < 2; mf++)
                #pragma unroll
                for (int nf = 0; nf < 8; nf++)
                    mma_f16(s[mf][nf][0], s[mf][nf][1], s[mf][nf][2], s[mf][nf][3],
                            qa[mf][ks][0], qa[mf][ks][1], qa[mf][ks][2], qa[mf][ks][3],
                            kb2[nf][0], kb2[nf][1]);
        }

        // ---- additive key mask (log2 domain) ----
        #pragma unroll
        for (int nf = 0; nf < 8; nf++) {
            int col = 8 * nf + 2 * tg;
            float m0 = (1.0f - Mb[col])     * NEGBIG_L2;
            float m1 = (1.0f - Mb[col + 1]) * NEGBIG_L2;
            #pragma unroll
            for (int mf = 0; mf < 2; mf++) {
                s[mf][nf][0] -= m0; s[mf][nf][1] -= m1;
                s[mf][nf][2] -= m0; s[mf][nf][3] -= m1;
            }
        }

        // ---- online softmax (base-2) ----
        #pragma unroll
        for (int mf = 0; mf < 2; mf++) {
            float rmax0 = -1e30f, rmax1 = -1e30f;
            #pragma unroll
            for (int nf = 0; nf < 8; nf++) {
                rmax0 = fmaxf(rmax0, fmaxf(s[mf][nf][0], s[mf][nf][1]));
                rmax1 = fmaxf(rmax1, fmaxf(s[mf][nf][2], s[mf][nf][3]));
            }
            #pragma unroll
            for (int off = 1; off <= 2; off <<= 1) {
                rmax0 = fmaxf(rmax0, __shfl_xor_sync(0xffffffffu, rmax0, off));
                rmax1 = fmaxf(rmax1, __shfl_xor_sync(0xffffffffu, rmax1, off));
            }
            float mn0 = fmaxf(m_i[2 * mf],     rmax0);
            float mn1 = fmaxf(m_i[2 * mf + 1], rmax1);
            float fi0 = ex2(m_i[2 * mf]     - mn0);
            float fi1 = ex2(m_i[2 * mf + 1] - mn1);
            m_i[2 * mf] = mn0; m_i[2 * mf + 1] = mn1;
            l_i[2 * mf] *= fi0; l_i[2 * mf + 1] *= fi1;
            #pragma unroll
            for (int nf = 0; nf < 8; nf++) {
                o[mf][nf][0] *= fi0; o[mf][nf][1] *= fi0;
                o[mf][nf][2] *= fi1; o[mf][nf][3] *= fi1;
            }
            float ls0 = 0.f, ls1 = 0.f;
            #pragma unroll
            for (int nf = 0; nf < 8; nf++) {
                s[mf][nf][0] = ex2(s[mf][nf][0] - mn0);
                s[mf][nf][1] = ex2(s[mf][nf][1] - mn0);
                s[mf][nf][2] = ex2(s[mf][nf][2] - mn1);
                s[mf][nf][3] = ex2(s[mf][nf][3] - mn1);
                ls0 += s[mf][nf][0] + s[mf][nf][1];
                ls1 += s[mf][nf][2] + s[mf][nf][3];
            }
            #pragma unroll
            for (int off = 1; off <= 2; off <<= 1) {
                ls0 += __shfl_xor_sync(0xffffffffu, ls0, off);
                ls1 += __shfl_xor_sync(0xffffffffu, ls1, off);
            }
            l_i[2 * mf] += ls0; l_i[2 * mf + 1] += ls1;
        }

        // ---- P -> smem (fp16), warp-private rows ----
        #pragma unroll
        for (int mf = 0; mf < 2; mf++) {
            int row = warp * 32 + mf * 16 + g;
            #pragma unroll
            for (int nf = 0; nf < 8; nf++) {
                int col = 8 * nf + 2 * tg;
                *(__half2*)&QP[row * ASTR + col] =
                    __floats2half2_rn(s[mf][nf][0], s[mf][nf][1]);
                *(__half2*)&QP[(row + 8) * ASTR + col] =
                    __floats2half2_rn(s[mf][nf][2], s[mf][nf][3]);
            }
        }
        __syncwarp();

        // ---- O += P @ V^T ----
        #pragma unroll
        for (int ks = 0; ks < 4; ks++) {
            u32 pa[2][4];
            #pragma unroll
            for (int mf = 0; mf < 2; mf++) {
                int row = warp * 32 + mf * 16 + r16;
                ldsm4(pa[mf][0], pa[mf][1], pa[mf][2], pa[mf][3],
                      su32(QP + row * ASTR) + ks * 32 + hi16);
            }
            u32 vb2[8][2];
            #pragma unroll
            for (int nfp = 0; nfp < 4; nfp++) {
                int row = nfp * 16 + r16;
                u32 r0, r1, r2, r3;
                ldsm4(r0, r1, r2, r3, su32(Vb + row * ASTR) + ks * 32 + hi16);
                vb2[2 * nfp][0] = r0;     vb2[2 * nfp][1] = r2;
                vb2[2 * nfp + 1][0] = r1; vb2[2 * nfp + 1][1] = r3;
            }
            #pragma unroll
            for (int mf = 0; mf < 2; mf++)
                #pragma unroll
                for (int nf = 0; nf < 8; nf++)
                    mma_f16(o[mf][nf][0], o[mf][nf][1], o[mf][nf][2], o[mf][nf][3],
                            pa[mf][0], pa[mf][1], pa[mf][2], pa[mf][3],
                            vb2[nf][0], vb2[nf][1]);
        }
        __syncthreads();
    }

    // ---- epilogue ----
    #pragma unroll
    for (int mf = 0; mf < 2; mf++) {
        int r0g = q0 + warp * 32 + mf * 16 + g;
        int r1g = r0g + 8;
        float inv0 = (l_i[2 * mf]     > 0.f) ? 1.0f / l_i[2 * mf]     : 0.f;
        float inv1 = (l_i[2 * mf + 1] > 0.f) ? 1.0f / l_i[2 * mf + 1] : 0.f;
        float qm0 = q_mask[b * SEQ + r0g] * inv0;
        float qm1 = q_mask[b * SEQ + r1g] * inv1;
        #pragma unroll
        for (int nf = 0; nf < 8; nf++) {
            int c = h * DH + 8 * nf + 2 * tg;
            *(float2*)&out[(size_t)(b * SEQ + r0g) * DIM + c] =
                make_float2(o[mf][nf][0] * qm0, o[mf][nf][1] * qm0);
            *(float2*)&out[(size_t)(b * SEQ + r1g) * DIM + c] =
                make_float2(o[mf][nf][2] * qm1, o[mf][nf][3] * qm1);
        }
    }
}

// ---------------------------------------------------------------------------
// Launch
// ---------------------------------------------------------------------------
extern "C" void kernel_launch(void* const* d_in, const int* in_sizes, int n_in,
                              void* d_out, int out_size)
{
    const float* q_value = (const float*)d_in[0];
    const float* k_value = (const float*)d_in[1];
    const float* v_value = (const float*)d_in[2];
    const float* v_mask  = (const float*)d_in[3];
    const float* q_mask  = (const float*)d_in[4];
    const float* Wq      = (const float*)d_in[5];
    const float* Wk      = (const float*)d_in[6];
    const float* Wv      = (const float*)d_in[7];
    float* out = (float*)d_out;

    __half *qw, *kw, *vwt, *wqt, *wkt, *wvt, *ah, *kh, *vh;
    cudaGetSymbolAddress((void**)&qw,  g_qw);
    cudaGetSymbolAddress((void**)&kw,  g_kw);
    cudaGetSymbolAddress((void**)&vwt, g_vwt);
    cudaGetSymbolAddress((void**)&wqt, g_wqt);
    cudaGetSymbolAddress((void**)&wkt, g_wkt);
    cudaGetSymbolAddress((void**)&wvt, g_wvt);
    cudaGetSymbolAddress((void**)&ah,  g_ah);
    cudaGetSymbolAddress((void**)&kh,  g_kh);
    cudaGetSymbolAddress((void**)&vh,  g_vh);

    int rGrid = (MTOT * DIM / 8) / 256;     // 4096
    round_kernel<<<rGrid, 256>>>((const float4*)q_value, (uint4*)ah);
    round_kernel<<<rGrid, 256>>>((const float4*)k_value, (uint4*)kh);
    round_kernel<<<rGrid, 256>>>((const float4*)v_value, (uint4*)vh);

    dim3 wtG(DIM / 32, DIM / 32), wtB(32, 8);
    wtrans_kernel<<<wtG, wtB>>>(Wq, wqt);
    wtrans_kernel<<<wtG, wtB>>>(Wk, wkt);
    wtrans_kernel<<<wtG, wtB>>>(Wv, wvt);

    const int proj_smem = 4 * PSTG * (int)sizeof(__half);   // 40960
    cudaFuncSetAttribute(proj_kernel,
                         cudaFuncAttributeMaxDynamicSharedMemorySize, proj_smem);
    dim3 pGrid(DIM / 128, MTOT / 128);   // (8, 64)
    proj_kernel<<<pGrid, 256, proj_smem>>>(ah, wqt, qw, 0, QSCL);
    proj_kernel<<<pGrid, 256, proj_smem>>>(kh, wkt, kw, 0, 1.0f);
    proj_kernel<<<pGrid, 256, proj_smem>>>(vh, wvt, vwt, 1, 1.0f);

    cudaFuncSetAttribute(attn_kernel,
                         cudaFuncAttributeMaxDynamicSharedMemorySize, A_SMEM_BYTES);
    dim3 aGrid(SEQ / 128, BATCH * HEADS);   // (16, 64)
    attn_kernel<<<aGrid, 128, A_SMEM_BYTES>>>(qw, kw, vwt, v_mask, q_mask, out);
}

// round 15
// speedup vs baseline: 1.8984x; 1.1244x over previous
#include <cuda_runtime.h>
#include <cuda_fp16.h>
#include <cstdint>

typedef unsigned int u32;

#define BATCH   4
#define SEQ     2048
#define DIM     1024
#define HEADS   16
#define DH      64
#define MTOT    (BATCH*SEQ)
#define LOG2E      1.4426950408889634f
#define NEGBIG_L2  1.4426950408889634e10f
#define QSCL       (0.125f * LOG2E)

// ---------------------------------------------------------------------------
// helpers
// ---------------------------------------------------------------------------
__device__ __forceinline__ float ex2(float x) {
    float r; asm("ex2.approx.ftz.f32 %0, %1;" : "=f"(r) : "f"(x)); return r;
}
__device__ __forceinline__ u32 su32(const void* p) {
    return (u32)__cvta_generic_to_shared(p);
}
__device__ __forceinline__ void ldsm4(u32 &r0, u32 &r1, u32 &r2, u32 &r3, u32 addr) {
    asm volatile("ldmatrix.sync.aligned.m8n8.x4.shared.b16 {%0,%1,%2,%3}, [%4];"
        : "=r"(r0), "=r"(r1), "=r"(r2), "=r"(r3) : "r"(addr));
}
__device__ __forceinline__ void mma_f16(float &c0, float &c1, float &c2, float &c3,
                                        u32 a0, u32 a1, u32 a2, u32 a3,
                                        u32 b0, u32 b1) {
    asm volatile("mma.sync.aligned.m16n8k16.row.col.f32.f16.f16.f32 "
                 "{%0,%1,%2,%3}, {%4,%5,%6,%7}, {%8,%9}, {%0,%1,%2,%3};"
        : "+f"(c0), "+f"(c1), "+f"(c2), "+f"(c3)
        : "r"(a0), "r"(a1), "r"(a2), "r"(a3), "r"(b0), "r"(b1));
}
__device__ __forceinline__ void cpa16(u32 dst, const void* src) {
    asm volatile("cp.async.cg.shared.global [%0], [%1], 16;" :: "r"(dst), "l"(src));
}
__device__ __forceinline__ void cpa4(u32 dst, const void* src) {
    asm volatile("cp.async.ca.shared.global [%0], [%1], 4;" :: "r"(dst), "l"(src));
}
__device__ __forceinline__ void cp_commit() {
    asm volatile("cp.async.commit_group;" ::: "memory");
}
__device__ __forceinline__ void cp_wait0() {
    asm volatile("cp.async.wait_group 0;" ::: "memory");
}
__device__ __forceinline__ u32 h2u(__half2 h) {
    u32 r; __builtin_memcpy(&r, &h, 4); return r;
}

// ---------------------------------------------------------------------------
// Scratch (all fp16)
// ---------------------------------------------------------------------------
__device__ __half g_qw[(size_t)MTOT * DIM];    // Q proj (pre-scaled by QSCL)
__device__ __half g_kw[(size_t)MTOT * DIM];    // K proj
__device__ __half g_vwt[(size_t)MTOT * DIM];   // V proj transposed [b][h][d][s]
__device__ __half g_wqt[(size_t)DIM * DIM];    // W^T
__device__ __half g_wkt[(size_t)DIM * DIM];
__device__ __half g_wvt[(size_t)DIM * DIM];
__device__ __half g_ah[(size_t)MTOT * DIM];    // fp16-rounded inputs
__device__ __half g_kh[(size_t)MTOT * DIM];
__device__ __half g_vh[(size_t)MTOT * DIM];

// ---------------------------------------------------------------------------
// fused elementwise fp32 -> fp16 pre-pass, 3 tensors in one launch
// ---------------------------------------------------------------------------
__global__ __launch_bounds__(256) void round_kernel(
    const float4* __restrict__ q, const float4* __restrict__ k,
    const float4* __restrict__ v,
    uint4* __restrict__ qo, uint4* __restrict__ ko, uint4* __restrict__ vo)
{
    const float4* in = (blockIdx.y == 0) ? q : (blockIdx.y == 1) ? k : v;
    uint4* out = (blockIdx.y == 0) ? qo : (blockIdx.y == 1) ? ko : vo;
    size_t i = (size_t)blockIdx.x * 256 + threadIdx.x;
    float4 v0 = in[2 * i], v1 = in[2 * i + 1];
    uint4 o;
    o.x = h2u(__floats2half2_rn(v0.x, v0.y));
    o.y = h2u(__floats2half2_rn(v0.z, v0.w));
    o.z = h2u(__floats2half2_rn(v1.x, v1.y));
    o.w = h2u(__floats2half2_rn(v1.z, v1.w));
    out[i] = o;
}

// ---------------------------------------------------------------------------
// fused W transpose + fp16 round: Wt[n][k] = h(W[k][n]), 3 weights in one launch
// ---------------------------------------------------------------------------
__global__ void wtrans_kernel(
    const float* __restrict__ Wq, const float* __restrict__ Wk,
    const float* __restrict__ Wv,
    __half* __restrict__ Wqt, __half* __restrict__ Wkt, __half* __restrict__ Wvt)
{
    const float* W = (blockIdx.z == 0) ? Wq : (blockIdx.z == 1) ? Wk : Wv;
    __half* Wt = (blockIdx.z == 0) ? Wqt : (blockIdx.z == 1) ? Wkt : Wvt;
    __shared__ float t[32][33];
    int n0 = blockIdx.x * 32, k0 = blockIdx.y * 32;
    int tx = threadIdx.x, ty = threadIdx.y;
    #pragma unroll
    for (int i = 0; i < 4; i++)
        t[ty + 8 * i][tx] = W[(size_t)(k0 + ty + 8 * i) * DIM + n0 + tx];
    __syncthreads();
    #pragma unroll
    for (int i = 0; i < 4; i++)
        Wt[(size_t)(n0 + ty + 8 * i) * DIM + k0 + tx] = __float2half_rn(t[tx][ty + 8 * i]);
}

// ---------------------------------------------------------------------------
// fp16 projection GEMM, 3 GEMMs fused via blockIdx.z.
// C = A @ Wt^T (fp32 accum), 128x128 tile, BK=32, 2-stage cp.async,
// 8 warps (4m x 2n), m16n8k16. z=0: Q (scaled QSCL); z=1: K; z=2: V transposed.
// ---------------------------------------------------------------------------
#define PSTR 40
#define PSTG (128 * PSTR)

__global__ __launch_bounds__(256, 2) void proj_kernel(
    const __half* __restrict__ A0, const __half* __restrict__ A1,
    const __half* __restrict__ A2,
    const __half* __restrict__ W0, const __half* __restrict__ W1,
    const __half* __restrict__ W2,
    __half* __restrict__ C0, __half* __restrict__ C1, __half* __restrict__ C2)
{
    extern __shared__ __half ps[];
    __half* As = ps;
    __half* Ws = ps + 2 * PSTG;

    const int z = blockIdx.z;
    const __half* A  = (z == 0) ? A0 : (z == 1) ? A1 : A2;
    const __half* Wt = (z == 0) ? W0 : (z == 1) ? W1 : W2;
    __half* C        = (z == 0) ? C0 : (z == 1) ? C1 : C2;
    const int vmode = (z == 2);
    const float oscale = (z == 0) ? QSCL : 1.0f;

    const int tid  = threadIdx.x;
    const int lane = tid & 31;
    const int warp = tid >> 5;
    const int wm = warp >> 1;
    const int wn = warp & 1;
    const int row0 = blockIdx.y * 128;
    const int col0 = blockIdx.x * 128;
    const int r16  = lane & 15;
    const int hi16 = (lane >> 4) * 16;

    float acc[2][8][4];
    #pragma unroll
    for (int i = 0; i < 2; i++)
        #pragma unroll
        for (int j = 0; j < 8; j++)
            #pragma unroll
            for (int r = 0; r < 4; r++) acc[i][j][r] = 0.f;

    {
        #pragma unroll
        for (int p = 0; p < 2; p++) {
            int idx = tid + p * 256;
            int r = idx >> 2, cb = idx & 3;
            cpa16(su32(As + r * PSTR + cb * 8), A  + (size_t)(row0 + r) * DIM + cb * 8);
            cpa16(su32(Ws + r * PSTR + cb * 8), Wt + (size_t)(col0 + r) * DIM + cb * 8);
        }
        cp_commit();
    }

    for (int t = 0; t < DIM / 32; t++) {
        int buf = t & 1;
        cp_wait0();
        __syncthreads();
        if (t < DIM / 32 - 1) {
            int kt = (t + 1) * 32;
            __half* Ad = As + (buf ^ 1) * PSTG;
            __half* Wd = Ws + (buf ^ 1) * PSTG;
            #pragma unroll
            for (int p = 0; p < 2; p++) {
                int idx = tid + p * 256;
                int r = idx >> 2, cb = idx & 3;
                cpa16(su32(Ad + r * PSTR + cb * 8), A  + (size_t)(row0 + r) * DIM + kt + cb * 8);
                cpa16(su32(Wd + r * PSTR + cb * 8), Wt + (size_t)(col0 + r) * DIM + kt + cb * 8);
            }
            cp_commit();
        }
        __half* Ab = As + buf * PSTG;
        __half* Wb = Ws + buf * PSTG;

        #pragma unroll
        for (int ks = 0; ks < 2; ks++) {
            u32 a[2][4];
            #pragma unroll
            for (int mf = 0; mf < 2; mf++) {
                int row = wm * 32 + mf * 16 + r16;
                ldsm4(a[mf][0], a[mf][1], a[mf][2], a[mf][3],
                      su32(Ab + row * PSTR) + ks * 32 + hi16);
            }
            u32 b[8][2];
            #pragma unroll
            for (int nfp = 0; nfp < 4; nfp++) {
                int row = wn * 64 + nfp * 16 + r16;
                u32 r0, r1, r2, r3;
                ldsm4(r0, r1, r2, r3, su32(Wb + row * PSTR) + ks * 32 + hi16);
                b[2 * nfp][0] = r0;     b[2 * nfp][1] = r2;
                b[2 * nfp + 1][0] = r1; b[2 * nfp + 1][1] = r3;
            }
            #pragma unroll
            for (int mf = 0; mf < 2; mf++)
                #pragma unroll
                for (int nf = 0; nf < 8; nf++)
                    mma_f16(acc[mf][nf][0], acc[mf][nf][1], acc[mf][nf][2], acc[mf][nf][3],
                            a[mf][0], a[mf][1], a[mf][2], a[mf][3],
                            b[nf][0], b[nf][1]);
        }
        __syncthreads();
    }

    const int g = lane >> 2;
    const int tg = lane & 3;
    if (!vmode) {
        #pragma unroll
        for (int mf = 0; mf < 2; mf++) {
            int r = row0 + wm * 32 + mf * 16 + g;
            #pragma unroll
            for (int nf = 0; nf < 8; nf++) {
                int c = col0 + wn * 64 + 8 * nf + 2 * tg;
                *(__half2*)&C[(size_t)r * DIM + c] =
                    __floats2half2_rn(acc[mf][nf][0] * oscale, acc[mf][nf][1] * oscale);
                *(__half2*)&C[(size_t)(r + 8) * DIM + c] =
                    __floats2half2_rn(acc[mf][nf][2] * oscale, acc[mf][nf][3] * oscale);
            }
        }
    } else {
        #pragma unroll
        for (int mf = 0; mf < 2; mf++) {
            int r = row0 + wm * 32 + mf * 16 + g;
            int bb = r >> 11, s1 = r & (SEQ - 1);
            #pragma unroll
            for (int nf = 0; nf < 8; nf++) {
                int c = col0 + wn * 64 + 8 * nf + 2 * tg;
                int h = c >> 6, d = c & 63;
                size_t base = ((size_t)(bb * HEADS + h) * DH + d) * SEQ + s1;
                C[base]           = __float2half_rn(acc[mf][nf][0]);
                C[base + SEQ]     = __float2half_rn(acc[mf][nf][1]);
                C[base + 8]       = __float2half_rn(acc[mf][nf][2]);
                C[base + SEQ + 8] = __float2half_rn(acc[mf][nf][3]);
            }
        }
    }
}

// ---------------------------------------------------------------------------
// fp16 flash attention: 128 thr / 4 warps, BQ=128, BKV=64, 2-stage cp.async.
// P NEVER touches smem: QK^T accumulator fragments repack in-register into
// the PV A-operand layout (fp16 C->A fragment identity).
// smem: Q[128*72] | K[2][64*72] | V[2][64*72] halfs | mask[2][64] floats
// ---------------------------------------------------------------------------
#define ASTR 72
#define AQP_B 0
#define AK_B  (128 * ASTR * 2)
#define AV_B  (AK_B + 2 * 64 * ASTR * 2)
#define AM_B  (AV_B + 2 * 64 * ASTR * 2)
#define A_SMEM_BYTES (AM_B + 2 * 64 * 4)

__global__ __launch_bounds__(128) void attn_kernel(
    const __half* __restrict__ qw,
    const __half* __restrict__ kw,
    const __half* __restrict__ vwt,
    const float* __restrict__ v_mask,
    const float* __restrict__ q_mask,
    float* __restrict__ out)
{
    extern __shared__ char asm_[];
    __half* QP  = (__half*)(asm_ + AQP_B);
    __half* Ksm = (__half*)(asm_ + AK_B);
    __half* Vsm = (__half*)(asm_ + AV_B);
    float*  Msm = (float*)(asm_ + AM_B);

    const int tid  = threadIdx.x;
    const int lane = tid & 31;
    const int warp = tid >> 5;
    const int g  = lane >> 2;
    const int tg = lane & 3;
    const int q0 = blockIdx.x * 128;
    const int bh = blockIdx.y;
    const int b = bh / HEADS;
    const int h = bh % HEADS;
    const int r16  = lane & 15;
    const int hi16 = (lane >> 4) * 16;

    const __half* qbase  = qw  + (size_t)(b * SEQ + q0) * DIM + h * DH;
    const __half* kbase0 = kw  + (size_t)(b * SEQ) * DIM + h * DH;
    const __half* vtbase = vwt + (size_t)(b * HEADS + h) * DH * SEQ;

    // ---- Q tile -> smem (QSCL pre-folded at projection) ----
    #pragma unroll
    for (int p = 0; p < 8; p++) {
        int idx = tid + p * 128;
        int r = idx >> 3, cb = idx & 7;
        cpa16(su32(QP + r * ASTR + cb * 8), qbase + (size_t)r * DIM + cb * 8);
    }
    cp_commit(); cp_wait0();
    __syncthreads();

    // ---- Q fragments: 2 m-frags x 4 k16-steps, register resident ----
    u32 qa[2][4][4];
    #pragma unroll
    for (int mf = 0; mf < 2; mf++)
        #pragma unroll
        for (int ks = 0; ks < 4; ks++) {
            int row = warp * 32 + mf * 16 + r16;
            ldsm4(qa[mf][ks][0], qa[mf][ks][1], qa[mf][ks][2], qa[mf][ks][3],
                  su32(QP + row * ASTR) + ks * 32 + hi16);
        }
    __syncthreads();

    float m_i[4] = {-1e30f, -1e30f, -1e30f, -1e30f};
    float l_i[4] = {0.f, 0.f, 0.f, 0.f};
    float o[2][8][4];
    #pragma unroll
    for (int mf = 0; mf < 2; mf++)
        #pragma unroll
        for (int nf = 0; nf < 8; nf++)
            #pragma unroll
            for (int r = 0; r < 4; r++) o[mf][nf][r] = 0.f;

    // stage-0 issue
    {
        #pragma unroll
        for (int p = 0; p < 4; p++) {
            int idx = tid + p * 128;
            int r = idx >> 3, cb = idx & 7;
            cpa16(su32(Ksm + r * ASTR + cb * 8), kbase0 + (size_t)r * DIM + cb * 8);
            cpa16(su32(Vsm + r * ASTR + cb * 8), vtbase + (size_t)r * SEQ + cb * 8);
        }
        if (tid < 64) cpa4(su32(Msm + tid), v_mask + b * SEQ + tid);
        cp_commit();
    }

    for (int kt = 0; kt < SEQ / 64; kt++) {
        int buf = kt & 1;
        cp_wait0();
        __syncthreads();
        if (kt < SEQ / 64 - 1) {
            int c1 = (kt + 1) * 64;
            __half* Kd = Ksm + (buf ^ 1) * 64 * ASTR;
            __half* Vd = Vsm + (buf ^ 1) * 64 * ASTR;
            const __half* kb = kbase0 + (size_t)c1 * DIM;
            #pragma unroll
            for (int p = 0; p < 4; p++) {
                int idx = tid + p * 128;
                int r = idx >> 3, cb = idx & 7;
                cpa16(su32(Kd + r * ASTR + cb * 8), kb + (size_t)r * DIM + cb * 8);
                cpa16(su32(Vd + r * ASTR + cb * 8), vtbase + (size_t)r * SEQ + c1 + cb * 8);
            }
            if (tid < 64) cpa4(su32(Msm + (buf ^ 1) * 64 + tid), v_mask + b * SEQ + c1 + tid);
            cp_commit();
        }
        __half* Kb = Ksm + buf * 64 * ASTR;
        __half* Vb = Vsm + buf * 64 * ASTR;
        float*  Mb = Msm + buf * 64;

        // ---- S = Q K^T (log2 domain) ----
        float s[2][8][4];
        #pragma unroll
        for (int mf = 0; mf < 2; mf++)
            #pragma unroll
            for (int nf = 0; nf < 8; nf++)
                #pragma unroll
                for (int r = 0; r < 4; r++) s[mf][nf][r] = 0.f;

        #pragma unroll
        for (int ks = 0; ks < 4; ks++) {
            u32 kb2[8][2];
            #pragma unroll
            for (int nfp = 0; nfp < 4; nfp++) {
                int row = nfp * 16 + r16;
                u32 r0, r1, r2, r3;
                ldsm4(r0, r1, r2, r3, su32(Kb + row * ASTR) + ks * 32 + hi16);
                kb2[2 * nfp][0] = r0;     kb2[2 * nfp][1] = r2;
                kb2[2 * nfp + 1][0] = r1; kb2[2 * nfp + 1][1] = r3;
            }
            #pragma unroll
            for (int mf = 0; mf < 2; mf++)
                #pragma unroll
                for (int nf = 0; nf < 8; nf++)
                    mma_f16(s[mf][nf][0], s[mf][nf][1], s[mf][nf][2], s[mf][nf][3],
                            qa[mf][ks][0], qa[mf][ks][1], qa[mf][ks][2], qa[mf][ks][3],
                            kb2[nf][0], kb2[nf][1]);
        }

        // ---- additive key mask (log2 domain) ----
        #pragma unroll
        for (int nf = 0; nf < 8; nf++) {
            int col = 8 * nf + 2 * tg;
            float m0 = (1.0f - Mb[col])     * NEGBIG_L2;
            float m1 = (1.0f - Mb[col + 1]) * NEGBIG_L2;
            #pragma unroll
            for (int mf = 0; mf < 2; mf++) {
                s[mf][nf][0] -= m0; s[mf][nf][1] -= m1;
                s[mf][nf][2] -= m0; s[mf][nf][3] -= m1;
            }
        }

        // ---- online softmax (base-2) ----
        #pragma unroll
        for (int mf = 0; mf < 2; mf++) {
            float rmax0 = -1e30f, rmax1 = -1e30f;
            #pragma unroll
            for (int nf = 0; nf < 8; nf++) {
                rmax0 = fmaxf(rmax0, fmaxf(s[mf][nf][0], s[mf][nf][1]));
                rmax1 = fmaxf(rmax1, fmaxf(s[mf][nf][2], s[mf][nf][3]));
            }
            #pragma unroll
            for (int off = 1; off <= 2; off <<= 1) {
                rmax0 = fmaxf(rmax0, __shfl_xor_sync(0xffffffffu, rmax0, off));
                rmax1 = fmaxf(rmax1, __shfl_xor_sync(0xffffffffu, rmax1, off));
            }
            float mn0 = fmaxf(m_i[2 * mf],     rmax0);
            float mn1 = fmaxf(m_i[2 * mf + 1], rmax1);
            float fi0 = ex2(m_i[2 * mf]     - mn0);
            float fi1 = ex2(m_i[2 * mf + 1] - mn1);
            m_i[2 * mf] = mn0; m_i[2 * mf + 1] = mn1;
            l_i[2 * mf] *= fi0; l_i[2 * mf + 1] *= fi1;
            #pragma unroll
            for (int nf = 0; nf < 8; nf++) {
                o[mf][nf][0] *= fi0; o[mf][nf][1] *= fi0;
                o[mf][nf][2] *= fi1; o[mf][nf][3] *= fi1;
            }
            float ls0 = 0.f, ls1 = 0.f;
            #pragma unroll
            for (int nf = 0; nf < 8; nf++) {
                s[mf][nf][0] = ex2(s[mf][nf][0] - mn0);
                s[mf][nf][1] = ex2(s[mf][nf][1] - mn0);
                s[mf][nf][2] = ex2(s[mf][nf][2] - mn1);
                s[mf][nf][3] = ex2(s[mf][nf][3] - mn1);
                ls0 += s[mf][nf][0] + s[mf][nf][1];
                ls1 += s[mf][nf][2] + s[mf][nf][3];
            }
            #pragma unroll
            for (int off = 1; off <= 2; off <<= 1) {
                ls0 += __shfl_xor_sync(0xffffffffu, ls0, off);
                ls1 += __shfl_xor_sync(0xffffffffu, ls1, off);
            }
            l_i[2 * mf] += ls0; l_i[2 * mf + 1] += ls1;
        }

        // ---- O += P @ V^T : P built in-register (C->A fragment identity) ----
        #pragma unroll
        for (int ks = 0; ks < 4; ks++) {
            u32 pa[2][4];
            #pragma unroll
            for (int mf = 0; mf < 2; mf++) {
                pa[mf][0] = h2u(__floats2half2_rn(s[mf][2 * ks][0],     s[mf][2 * ks][1]));
                pa[mf][1] = h2u(__floats2half2_rn(s[mf][2 * ks][2],     s[mf][2 * ks][3]));
                pa[mf][2] = h2u(__floats2half2_rn(s[mf][2 * ks + 1][0], s[mf][2 * ks + 1][1]));
                pa[mf][3] = h2u(__floats2half2_rn(s[mf][2 * ks + 1][2], s[mf][2 * ks + 1][3]));
            }
            u32 vb2[8][2];
            #pragma unroll
            for (int nfp = 0; nfp < 4; nfp++) {
                int row = nfp * 16 + r16;
                u32 r0, r1, r2, r3;
                ldsm4(r0, r1, r2, r3, su32(Vb + row * ASTR) + ks * 32 + hi16);
                vb2[2 * nfp][0] = r0;     vb2[2 * nfp][1] = r2;
                vb2[2 * nfp + 1][0] = r1; vb2[2 * nfp + 1][1] = r3;
            }
            #pragma unroll
            for (int mf = 0; mf < 2; mf++)
                #pragma unroll
                for (int nf = 0; nf < 8; nf++)
                    mma_f16(o[mf][nf][0], o[mf][nf][1], o[mf][nf][2], o[mf][nf][3],
                            pa[mf][0], pa[mf][1], pa[mf][2], pa[mf][3],
                            vb2[nf][0], vb2[nf][1]);
        }
        __syncthreads();
    }

    // ---- epilogue ----
    #pragma unroll
    for (int mf = 0; mf < 2; mf++) {
        int r0g = q0 + warp * 32 + mf * 16 + g;
        int r1g = r0g + 8;
        float inv0 = (l_i[2 * mf]     > 0.f) ? 1.0f / l_i[2 * mf]     : 0.f;
        float inv1 = (l_i[2 * mf + 1] > 0.f) ? 1.0f / l_i[2 * mf + 1] : 0.f;
        float qm0 = q_mask[b * SEQ + r0g] * inv0;
        float qm1 = q_mask[b * SEQ + r1g] * inv1;
        #pragma unroll
        for (int nf = 0; nf < 8; nf++) {
            int c = h * DH + 8 * nf + 2 * tg;
            *(float2*)&out[(size_t)(b * SEQ + r0g) * DIM + c] =
                make_float2(o[mf][nf][0] * qm0, o[mf][nf][1] * qm0);
            *(float2*)&out[(size_t)(b * SEQ + r1g) * DIM + c] =
                make_float2(o[mf][nf][2] * qm1, o[mf][nf][3] * qm1);
        }
    }
}

// ---------------------------------------------------------------------------
// Launch
// ---------------------------------------------------------------------------
extern "C" void kernel_launch(void* const* d_in, const int* in_sizes, int n_in,
                              void* d_out, int out_size)
{
    const float* q_value = (const float*)d_in[0];
    const float* k_value = (const float*)d_in[1];
    const float* v_value = (const float*)d_in[2];
    const float* v_mask  = (const float*)d_in[3];
    const float* q_mask  = (const float*)d_in[4];
    const float* Wq      = (const float*)d_in[5];
    const float* Wk      = (const float*)d_in[6];
    const float* Wv      = (const float*)d_in[7];
    float* out = (float*)d_out;

    __half *qw, *kw, *vwt, *wqt, *wkt, *wvt, *ah, *kh, *vh;
    cudaGetSymbolAddress((void**)&qw,  g_qw);
    cudaGetSymbolAddress((void**)&kw,  g_kw);
    cudaGetSymbolAddress((void**)&vwt, g_vwt);
    cudaGetSymbolAddress((void**)&wqt, g_wqt);
    cudaGetSymbolAddress((void**)&wkt, g_wkt);
    cudaGetSymbolAddress((void**)&wvt, g_wvt);
    cudaGetSymbolAddress((void**)&ah,  g_ah);
    cudaGetSymbolAddress((void**)&kh,  g_kh);
    cudaGetSymbolAddress((void**)&vh,  g_vh);

    dim3 rGrid((MTOT * DIM / 8) / 256, 3);    // (4096, 3)
    round_kernel<<<rGrid, 256>>>((const float4*)q_value, (const float4*)k_value,
                                 (const float4*)v_value,
                                 (uint4*)ah, (uint4*)kh, (uint4*)vh);

    dim3 wtG(DIM / 32, DIM / 32, 3), wtB(32, 8);
    wtrans_kernel<<<wtG, wtB>>>(Wq, Wk, Wv, wqt, wkt, wvt);

    const int proj_smem = 4 * PSTG * (int)sizeof(__half);   // 40960
    cudaFuncSetAttribute(proj_kernel,
                         cudaFuncAttributeMaxDynamicSharedMemorySize, proj_smem);
    dim3 pGrid(DIM / 128, MTOT / 128, 3);   // (8, 64, 3)
    proj_kernel<<<pGrid, 256, proj_smem>>>(ah, kh, vh, wqt, wkt, wvt, qw, kw, vwt);

    cudaFuncSetAttribute(attn_kernel,
                         cudaFuncAttributeMaxDynamicSharedMemorySize, A_SMEM_BYTES);
    dim3 aGrid(SEQ / 128, BATCH * HEADS);   // (16, 64)
    attn_kernel<<<aGrid, 128, A_SMEM_BYTES>>>(qw, kw, vwt, v_mask, q_mask, out);
}